// round 15
// baseline (speedup 1.0000x reference)
#include <cuda_runtime.h>
#include <cstdint>
#include <math.h>

#define EPSF 1e-5f

static constexpr int Hdim = 2048;   // hidden
static constexpr int Idim = 8192;   // intermediate
static constexpr int Tdim = 4096;   // B*S tokens
static constexpr int WELEMS = Hdim * Idim;

// ---------------- device scratch (no allocations allowed) ----------------
__device__ __align__(16) int8_t g_wq_gate[WELEMS];
__device__ __align__(16) int8_t g_wq_up[WELEMS];
__device__ __align__(16) int8_t g_wq_down[WELEMS];
__device__ __align__(16) int8_t g_xq[Tdim * Hdim];
__device__ float  g_xs[Tdim];
__device__ __align__(16) float  g_h[(size_t)Tdim * Idim];
__device__ __align__(16) int8_t g_hq[(size_t)Tdim * Idim];
__device__ float  g_hs[Tdim];
__device__ float  g_part[3 * 1024];
__device__ float  g_wscale[3];

// ---------------- small PTX helpers ----------------
__device__ __forceinline__ uint32_t smem_u32(const void* p) {
    return (uint32_t)__cvta_generic_to_shared(p);
}
__device__ __forceinline__ void cp_async16(uint32_t saddr, const void* gptr) {
    asm volatile("cp.async.cg.shared.global [%0], [%1], 16;\n" :: "r"(saddr), "l"(gptr));
}
__device__ __forceinline__ void cp_commit() {
    asm volatile("cp.async.commit_group;\n" ::: "memory");
}
template<int N>
__device__ __forceinline__ void cp_wait() {
    asm volatile("cp.async.wait_group %0;\n" :: "n"(N) : "memory");
}
__device__ __forceinline__ void ldsm_x4(uint32_t& r0, uint32_t& r1, uint32_t& r2, uint32_t& r3, uint32_t addr) {
    asm volatile("ldmatrix.sync.aligned.m8n8.x4.shared.b16 {%0,%1,%2,%3}, [%4];\n"
                 : "=r"(r0), "=r"(r1), "=r"(r2), "=r"(r3) : "r"(addr));
}
__device__ __forceinline__ void mma_s8(int* c, const uint32_t* a, const uint32_t* b) {
    asm volatile("mma.sync.aligned.m16n8k32.row.col.s32.s8.s8.s32 "
                 "{%0,%1,%2,%3}, {%4,%5,%6,%7}, {%8,%9}, {%0,%1,%2,%3};\n"
                 : "+r"(c[0]), "+r"(c[1]), "+r"(c[2]), "+r"(c[3])
                 : "r"(a[0]), "r"(a[1]), "r"(a[2]), "r"(a[3]), "r"(b[0]), "r"(b[1]));
}
__device__ __forceinline__ void dp4x4(int& acc, const int4& a, const int4& b) {
    acc = __dp4a(a.x, b.x, acc);
    acc = __dp4a(a.y, b.y, acc);
    acc = __dp4a(a.z, b.z, acc);
    acc = __dp4a(a.w, b.w, acc);
}

// ---------------- merged weight-scale partial sums (grid.y = widx) ----------------
__global__ void abs_sum_partial_kernel(const float4* __restrict__ w0,
                                       const float4* __restrict__ w1,
                                       const float4* __restrict__ w2) {
    __shared__ float sd[256];
    int widx = blockIdx.y;
    const float4* w4 = (widx == 0) ? w0 : (widx == 1) ? w1 : w2;
    int t = threadIdx.x;
    const float4* p = w4 + (size_t)blockIdx.x * 4096;
    float s = 0.f;
    #pragma unroll 4
    for (int i = t; i < 4096; i += 256) {
        float4 v = p[i];
        s += fabsf(v.x) + fabsf(v.y) + fabsf(v.z) + fabsf(v.w);
    }
    sd[t] = s;
    __syncthreads();
    for (int o = 128; o > 0; o >>= 1) {
        if (t < o) sd[t] += sd[t + o];
        __syncthreads();
    }
    if (t == 0) g_part[widx * 1024 + blockIdx.x] = sd[0];
}

__global__ void finalize_scales_kernel() {
    __shared__ float sd[256];
    int t = threadIdx.x;
    for (int w = 0; w < 3; ++w) {
        float s = g_part[w * 1024 + t] + g_part[w * 1024 + t + 256]
                + g_part[w * 1024 + t + 512] + g_part[w * 1024 + t + 768];
        sd[t] = s;
        __syncthreads();
        for (int o = 128; o > 0; o >>= 1) {
            if (t < o) sd[t] += sd[t + o];
            __syncthreads();
        }
        if (t == 0) {
            float mean = sd[0] / (float)WELEMS;
            g_wscale[w] = fmaxf(mean, EPSF);
        }
        __syncthreads();
    }
}

// ---------------- merged kernel: weight quant (y<3) + FWHT/quant of x (y==3) ----------------
__global__ __launch_bounds__(256)
void quant_fwht_kernel(const float4* __restrict__ w0,
                       const float4* __restrict__ w1,
                       const float4* __restrict__ w2,
                       const float4* __restrict__ x) {
    constexpr int N = 2048;
    constexpr int T = 256;
    constexpr int Q4 = N / 4;
    __shared__ float4 buf4[Q4];
    __shared__ float red[T / 32];

    const int t = threadIdx.x;

    if (blockIdx.y < 3) {
        if (blockIdx.x >= 2048) return;
        int widx = blockIdx.y;
        const float4* w4 = (widx == 0) ? w0 : (widx == 1) ? w1 : w2;
        char4* dst = (char4*)((widx == 0) ? g_wq_gate : (widx == 1) ? g_wq_up : g_wq_down);
        const float inv = 1.0f / g_wscale[widx];
        const int n4 = WELEMS / 4;
        const int stride = 2048 * 256;
        for (int i = blockIdx.x * 256 + t; i < n4; i += stride) {
            float4 v = w4[i];
            char4 o;
            o.x = (int8_t)fminf(fmaxf(rintf(v.x * inv), -1.f), 1.f);
            o.y = (int8_t)fminf(fmaxf(rintf(v.y * inv), -1.f), 1.f);
            o.z = (int8_t)fminf(fmaxf(rintf(v.z * inv), -1.f), 1.f);
            o.w = (int8_t)fminf(fmaxf(rintf(v.w * inv), -1.f), 1.f);
            dst[i] = o;
        }
        return;
    }

    const size_t row = blockIdx.x;
    const float4* xr = x + row * Q4;
    char4* q4 = (char4*)g_xq;

    float4 a = xr[2 * t], b = xr[2 * t + 1];
    float4 ta = make_float4(a.x + a.y, a.x - a.y, a.z + a.w, a.z - a.w);
    float4 tb = make_float4(b.x + b.y, b.x - b.y, b.z + b.w, b.z - b.w);
    a = make_float4(ta.x + ta.z, ta.y + ta.w, ta.x - ta.z, ta.y - ta.w);
    b = make_float4(tb.x + tb.z, tb.y + tb.w, tb.x - tb.z, tb.y - tb.w);
    buf4[2 * t] = a;
    buf4[2 * t + 1] = b;
    __syncthreads();

    #pragma unroll
    for (int hv = 1; hv <= N / 16; hv <<= 1) {
        int i4 = ((t & ~(hv - 1)) << 1) | (t & (hv - 1));
        float4 va = buf4[i4], vb = buf4[i4 + hv];
        buf4[i4]      = make_float4(va.x + vb.x, va.y + vb.y, va.z + vb.z, va.w + vb.w);
        buf4[i4 + hv] = make_float4(va.x - vb.x, va.y - vb.y, va.z - vb.z, va.w - vb.w);
        __syncthreads();
    }

    float4 va = buf4[t], vb = buf4[t + N / 8];
    const float c = (float)(1.0 / sqrt((double)N));
    float v0 = (va.x + vb.x) * c, v1 = (va.y + vb.y) * c;
    float v2 = (va.z + vb.z) * c, v3 = (va.w + vb.w) * c;
    float v4 = (va.x - vb.x) * c, v5 = (va.y - vb.y) * c;
    float v6 = (va.z - vb.z) * c, v7 = (va.w - vb.w) * c;

    float m = fmaxf(fmaxf(fmaxf(fabsf(v0), fabsf(v1)), fmaxf(fabsf(v2), fabsf(v3))),
                    fmaxf(fmaxf(fabsf(v4), fabsf(v5)), fmaxf(fabsf(v6), fabsf(v7))));
    #pragma unroll
    for (int o = 16; o; o >>= 1) m = fmaxf(m, __shfl_xor_sync(0xffffffffu, m, o));
    if ((t & 31) == 0) red[t >> 5] = m;
    __syncthreads();
    if (t < 32) {
        m = (t < T / 32) ? red[t] : 0.f;
        #pragma unroll
        for (int o = 16; o; o >>= 1) m = fmaxf(m, __shfl_xor_sync(0xffffffffu, m, o));
        if (t == 0) red[0] = fmaxf(m, EPSF);
    }
    __syncthreads();
    float absmax = red[0];
    float scale = 127.f / absmax;
    if (t == 0) g_xs[row] = absmax / 127.f;

    char4 o0, o1;
    o0.x = (int8_t)fminf(fmaxf(rintf(v0 * scale), -128.f), 127.f);
    o0.y = (int8_t)fminf(fmaxf(rintf(v1 * scale), -128.f), 127.f);
    o0.z = (int8_t)fminf(fmaxf(rintf(v2 * scale), -128.f), 127.f);
    o0.w = (int8_t)fminf(fmaxf(rintf(v3 * scale), -128.f), 127.f);
    o1.x = (int8_t)fminf(fmaxf(rintf(v4 * scale), -128.f), 127.f);
    o1.y = (int8_t)fminf(fmaxf(rintf(v5 * scale), -128.f), 127.f);
    o1.z = (int8_t)fminf(fmaxf(rintf(v6 * scale), -128.f), 127.f);
    o1.w = (int8_t)fminf(fmaxf(rintf(v7 * scale), -128.f), 127.f);
    q4[row * Q4 + t] = o0;
    q4[row * Q4 + t + N / 8] = o1;
}

// ---------------- FWHT(8192) + per-token int8 quant of h ----------------
__global__ __launch_bounds__(1024)
void fwht_quant_h_kernel() {
    constexpr int N = 8192;
    constexpr int T = N / 8;
    constexpr int Q4 = N / 4;
    __shared__ float4 buf4[Q4];
    __shared__ float red[T / 32];

    const float4* src4 = (const float4*)g_h;
    char4* q4 = (char4*)g_hq;

    const int t = threadIdx.x;
    const size_t row = blockIdx.x;
    const float4* x = src4 + row * Q4;

    float4 a = x[2 * t], b = x[2 * t + 1];
    float4 ta = make_float4(a.x + a.y, a.x - a.y, a.z + a.w, a.z - a.w);
    float4 tb = make_float4(b.x + b.y, b.x - b.y, b.z + b.w, b.z - b.w);
    a = make_float4(ta.x + ta.z, ta.y + ta.w, ta.x - ta.z, ta.y - ta.w);
    b = make_float4(tb.x + tb.z, tb.y + tb.w, tb.x - tb.z, tb.y - tb.w);
    buf4[2 * t] = a;
    buf4[2 * t + 1] = b;
    __syncthreads();

    #pragma unroll
    for (int hv = 1; hv <= N / 16; hv <<= 1) {
        int i4 = ((t & ~(hv - 1)) << 1) | (t & (hv - 1));
        float4 va = buf4[i4], vb = buf4[i4 + hv];
        buf4[i4]      = make_float4(va.x + vb.x, va.y + vb.y, va.z + vb.z, va.w + vb.w);
        buf4[i4 + hv] = make_float4(va.x - vb.x, va.y - vb.y, va.z - vb.z, va.w - vb.w);
        __syncthreads();
    }

    float4 va = buf4[t], vb = buf4[t + N / 8];
    const float c = (float)(1.0 / sqrt((double)N));
    float v0 = (va.x + vb.x) * c, v1 = (va.y + vb.y) * c;
    float v2 = (va.z + vb.z) * c, v3 = (va.w + vb.w) * c;
    float v4 = (va.x - vb.x) * c, v5 = (va.y - vb.y) * c;
    float v6 = (va.z - vb.z) * c, v7 = (va.w - vb.w) * c;

    float m = fmaxf(fmaxf(fmaxf(fabsf(v0), fabsf(v1)), fmaxf(fabsf(v2), fabsf(v3))),
                    fmaxf(fmaxf(fabsf(v4), fabsf(v5)), fmaxf(fabsf(v6), fabsf(v7))));
    #pragma unroll
    for (int o = 16; o; o >>= 1) m = fmaxf(m, __shfl_xor_sync(0xffffffffu, m, o));
    if ((t & 31) == 0) red[t >> 5] = m;
    __syncthreads();
    if (t < 32) {
        m = red[t];
        #pragma unroll
        for (int o = 16; o; o >>= 1) m = fmaxf(m, __shfl_xor_sync(0xffffffffu, m, o));
        if (t == 0) red[0] = fmaxf(m, EPSF);
    }
    __syncthreads();
    float absmax = red[0];
    float scale = 127.f / absmax;
    if (t == 0) g_hs[row] = absmax / 127.f;

    char4 o0, o1;
    o0.x = (int8_t)fminf(fmaxf(rintf(v0 * scale), -128.f), 127.f);
    o0.y = (int8_t)fminf(fmaxf(rintf(v1 * scale), -128.f), 127.f);
    o0.z = (int8_t)fminf(fmaxf(rintf(v2 * scale), -128.f), 127.f);
    o0.w = (int8_t)fminf(fmaxf(rintf(v3 * scale), -128.f), 127.f);
    o1.x = (int8_t)fminf(fmaxf(rintf(v4 * scale), -128.f), 127.f);
    o1.y = (int8_t)fminf(fmaxf(rintf(v5 * scale), -128.f), 127.f);
    o1.z = (int8_t)fminf(fmaxf(rintf(v6 * scale), -128.f), 127.f);
    o1.w = (int8_t)fminf(fmaxf(rintf(v7 * scale), -128.f), 127.f);
    q4[row * Q4 + t] = o0;
    q4[row * Q4 + t + N / 8] = o1;
}

// ================= K-ROTATION HYBRID GEMM 1 (wave-decorrelated) =================
// CTA 128M x 32 h-cols, 128 threads. Phase = (kt + warp + waveParity) & 1.
// waveParity = (linear_bid / 148) & 1: co-resident CTAs come from consecutive
// 148-CTA waves -> opposite parity -> each SMSP hosts one mma-phase and one
// dp4a-phase warp simultaneously.
__global__ __launch_bounds__(128)
void gemm1_imma_kernel() {
    extern __shared__ int8_t smem[];
    // per stage: A 128x128B @0 (16KB), Bg 32x128B @16384, Bu 32x128B @20480; stride 24576
    const int K = Hdim;
    const int tid = threadIdx.x;
    const int warp = tid >> 5, lane = tid & 31;
    const int mBase = blockIdx.y << 7;
    const int nBase = blockIdx.x << 5;
    const int bpar = (int)(((blockIdx.y * gridDim.x + blockIdx.x) / 148u) & 1u);
    const uint32_t sbase = smem_u32(smem);

    int accg[2][4][4] = {}, accu[2][4][4] = {};

    // loader: 128 threads; A 8 chunks, Bg/Bu 2 chunks each
    const int8_t* gA[8]; uint32_t oA[8];
    #pragma unroll
    for (int j = 0; j < 8; ++j) {
        int i = tid + 128 * j;
        int row = i >> 3, ch = i & 7;
        gA[j] = g_xq + (size_t)(mBase + row) * K + ch * 16;
        oA[j] = row * 128 + ((ch ^ (row & 7)) << 4);
    }
    const int8_t* gG[2]; const int8_t* gU[2]; uint32_t oB[2];
    #pragma unroll
    for (int j = 0; j < 2; ++j) {
        int i = tid + 128 * j;
        int row = i >> 3, ch = i & 7;
        gG[j] = g_wq_gate + (size_t)(nBase + row) * K + ch * 16;
        gU[j] = g_wq_up   + (size_t)(nBase + row) * K + ch * 16;
        oB[j] = row * 128 + ((ch ^ (row & 7)) << 4);
    }
    auto load_stage = [&](int stage, int kt) {
        uint32_t sst = sbase + stage * 24576;
        #pragma unroll
        for (int j = 0; j < 8; ++j) cp_async16(sst + oA[j], gA[j] + kt);
        #pragma unroll
        for (int j = 0; j < 2; ++j) cp_async16(sst + 16384 + oB[j], gG[j] + kt);
        #pragma unroll
        for (int j = 0; j < 2; ++j) cp_async16(sst + 20480 + oB[j], gU[j] + kt);
    };

    // mma-path addressing
    uint32_t rowOffA[2], rx7A[2];
    #pragma unroll
    for (int mt = 0; mt < 2; ++mt) {
        int r = warp * 32 + mt * 16 + (lane & 15);
        rowOffA[mt] = r * 128; rx7A[mt] = r & 7;
    }
    uint32_t rowOffB[2], rx7B[2];
    #pragma unroll
    for (int g = 0; g < 2; ++g) {
        int r = g * 16 + (lane & 15);
        rowOffB[g] = r * 128; rx7B[g] = r & 7;
    }
    const uint32_t laneHi = lane >> 4;
    // dp4a-path addressing
    const int lr = lane >> 2, lc = (lane & 3) * 2;

    const int iters = K / 128;  // 16
    load_stage(0, 0); cp_commit();
    load_stage(1, 128); cp_commit();

    for (int kt = 0; kt < iters; ++kt) {
        cp_wait<1>();
        __syncthreads();
        int nk = kt + 2;
        if (nk < iters) load_stage(nk % 3, nk * 128);
        cp_commit();

        if (((kt + warp + bpar) & 1) == 0) {
            // ---------- tensor-pipe k-tile ----------
            uint32_t sst = sbase + (kt % 3) * 24576;
            #pragma unroll
            for (int s = 0; s < 4; ++s) {
                uint32_t ch = 2 * s + laneHi;
                uint32_t af[2][4];
                #pragma unroll
                for (int mt = 0; mt < 2; ++mt)
                    ldsm_x4(af[mt][0], af[mt][1], af[mt][2], af[mt][3],
                            sst + rowOffA[mt] + ((ch ^ rx7A[mt]) << 4));
                uint32_t bg[4][2], bu[4][2];
                #pragma unroll
                for (int g = 0; g < 2; ++g) {
                    uint32_t r0, r1, r2, r3;
                    ldsm_x4(r0, r1, r2, r3, sst + 16384 + rowOffB[g] + ((ch ^ rx7B[g]) << 4));
                    bg[2 * g][0] = r0; bg[2 * g][1] = r2;
                    bg[2 * g + 1][0] = r1; bg[2 * g + 1][1] = r3;
                    ldsm_x4(r0, r1, r2, r3, sst + 20480 + rowOffB[g] + ((ch ^ rx7B[g]) << 4));
                    bu[2 * g][0] = r0; bu[2 * g][1] = r2;
                    bu[2 * g + 1][0] = r1; bu[2 * g + 1][1] = r3;
                }
                #pragma unroll
                for (int mt = 0; mt < 2; ++mt)
                    #pragma unroll
                    for (int nt = 0; nt < 4; ++nt) {
                        mma_s8(accg[mt][nt], af[mt], bg[nt]);
                        mma_s8(accu[mt][nt], af[mt], bu[nt]);
                    }
            }
        } else {
            // ---------- dp4a (fma-pipe) k-tile: same fragment elements ----------
            const int8_t* sp = smem + (kt % 3) * 24576;
            #pragma unroll 1
            for (int ph = 0; ph < 8; ++ph) {
                int4 av[4];
                #pragma unroll
                for (int mt = 0; mt < 2; ++mt)
                    #pragma unroll
                    for (int h = 0; h < 2; ++h) {
                        int row = warp * 32 + mt * 16 + lr + h * 8;
                        av[mt * 2 + h] = *(const int4*)(sp + row * 128 + ((ph ^ (row & 7)) << 4));
                    }
                const uint32_t swz0 = (uint32_t)((ph ^ lc) << 4);
                const uint32_t swz1 = (uint32_t)((ph ^ (lc + 1)) << 4);
                #pragma unroll
                for (int nt = 0; nt < 4; ++nt) {
                    int c0 = nt * 8 + lc;
                    int4 bg0 = *(const int4*)(sp + 16384 + c0 * 128 + swz0);
                    int4 bg1 = *(const int4*)(sp + 16384 + (c0 + 1) * 128 + swz1);
                    int4 bu0 = *(const int4*)(sp + 20480 + c0 * 128 + swz0);
                    int4 bu1 = *(const int4*)(sp + 20480 + (c0 + 1) * 128 + swz1);
                    #pragma unroll
                    for (int mt = 0; mt < 2; ++mt)
                        #pragma unroll
                        for (int h = 0; h < 2; ++h) {
                            const int4& aa = av[mt * 2 + h];
                            dp4x4(accg[mt][nt][h * 2 + 0], aa, bg0);
                            dp4x4(accg[mt][nt][h * 2 + 1], aa, bg1);
                            dp4x4(accu[mt][nt][h * 2 + 0], aa, bu0);
                            dp4x4(accu[mt][nt][h * 2 + 1], aa, bu1);
                        }
                }
            }
        }
    }

    // epilogue: silu(gate)*up -> g_h
    const float wsg = g_wscale[0], wsu = g_wscale[1];
    const int r0 = lane >> 2, c0l = (lane & 3) * 2;
    #pragma unroll
    for (int mt = 0; mt < 2; ++mt) {
        #pragma unroll
        for (int half = 0; half < 2; ++half) {
            int row = mBase + warp * 32 + mt * 16 + r0 + 8 * half;
            float xs = g_xs[row];
            float fg = wsg * xs, fu = wsu * xs;
            #pragma unroll
            for (int nt = 0; nt < 4; ++nt) {
                int col = nBase + nt * 8 + c0l;
                float gv0 = (float)accg[mt][nt][2 * half]     * fg;
                float gv1 = (float)accg[mt][nt][2 * half + 1] * fg;
                float uv0 = (float)accu[mt][nt][2 * half]     * fu;
                float uv1 = (float)accu[mt][nt][2 * half + 1] * fu;
                float2 hv;
                hv.x = (gv0 / (1.f + expf(-gv0))) * uv0;
                hv.y = (gv1 / (1.f + expf(-gv1))) * uv1;
                *(float2*)&g_h[(size_t)row * Idim + col] = hv;
            }
        }
    }
}

// ================= K-ROTATION HYBRID GEMM 2 (wave-decorrelated): out = hq @ wdown^T =================
// CTA 64M x 64N, 128 threads (4 warps, warp tile 16M x 64N).
__global__ __launch_bounds__(128)
void gemm2_imma_kernel(float* __restrict__ out) {
    extern __shared__ int8_t smem[];
    // per stage: A 64x128B @0 (8KB), B 64x128B @8192 (8KB); stride 16384
    const int K = Idim;
    const int tid = threadIdx.x;
    const int warp = tid >> 5, lane = tid & 31;
    const int mBase = blockIdx.y << 6;
    const int nBase = blockIdx.x << 6;
    const int bpar = (int)(((blockIdx.y * gridDim.x + blockIdx.x) / 148u) & 1u);
    const uint32_t sbase = smem_u32(smem);

    int acc[8][4] = {};

    const int8_t* gA[4]; const int8_t* gB[4]; uint32_t oA[4];
    #pragma unroll
    for (int j = 0; j < 4; ++j) {
        int i = tid + 128 * j;
        int row = i >> 3, ch = i & 7;              // rows 0..63
        gA[j] = g_hq      + (size_t)(mBase + row) * K + ch * 16;
        gB[j] = g_wq_down + (size_t)(nBase + row) * K + ch * 16;
        oA[j] = row * 128 + ((ch ^ (row & 7)) << 4);
    }
    auto load_stage = [&](int stage, int kt) {
        uint32_t sst = sbase + stage * 16384;
        #pragma unroll
        for (int j = 0; j < 4; ++j) cp_async16(sst + oA[j], gA[j] + kt);
        #pragma unroll
        for (int j = 0; j < 4; ++j) cp_async16(sst + 8192 + oA[j], gB[j] + kt);
    };

    // mma addressing
    const int rA = warp * 16 + (lane & 15);
    const uint32_t rowOffA = rA * 128, rx7A = rA & 7;
    uint32_t rowOffB[4], rx7B[4];
    #pragma unroll
    for (int g = 0; g < 4; ++g) {
        int r = g * 16 + (lane & 15);
        rowOffB[g] = 8192 + r * 128; rx7B[g] = r & 7;
    }
    const uint32_t laneHi = lane >> 4;
    const int lr = lane >> 2, lc = (lane & 3) * 2;

    const int iters = K / 128;  // 64
    load_stage(0, 0); cp_commit();
    load_stage(1, 128); cp_commit();

    for (int kt = 0; kt < iters; ++kt) {
        cp_wait<1>();
        __syncthreads();
        int nk = kt + 2;
        if (nk < iters) load_stage(nk % 3, nk * 128);
        cp_commit();

        if (((kt + warp + bpar) & 1) == 0) {
            // ---------- tensor-pipe k-tile ----------
            uint32_t sst = sbase + (kt % 3) * 16384;
            #pragma unroll
            for (int s = 0; s < 4; ++s) {
                uint32_t ch = 2 * s + laneHi;
                uint32_t af[4];
                ldsm_x4(af[0], af[1], af[2], af[3], sst + rowOffA + ((ch ^ rx7A) << 4));
                uint32_t bf[8][2];
                #pragma unroll
                for (int g = 0; g < 4; ++g) {
                    uint32_t r0, r1, r2, r3;
                    ldsm_x4(r0, r1, r2, r3, sst + rowOffB[g] + ((ch ^ rx7B[g]) << 4));
                    bf[2 * g][0] = r0; bf[2 * g][1] = r2;
                    bf[2 * g + 1][0] = r1; bf[2 * g + 1][1] = r3;
                }
                #pragma unroll
                for (int nt = 0; nt < 8; ++nt)
                    mma_s8(acc[nt], af, bf[nt]);
            }
        } else {
            // ---------- dp4a k-tile ----------
            const int8_t* sp = smem + (kt % 3) * 16384;
            #pragma unroll 1
            for (int ph = 0; ph < 8; ++ph) {
                int4 av[2];
                #pragma unroll
                for (int h = 0; h < 2; ++h) {
                    int row = warp * 16 + lr + h * 8;
                    av[h] = *(const int4*)(sp + row * 128 + ((ph ^ (row & 7)) << 4));
                }
                const uint32_t swz0 = (uint32_t)((ph ^ lc) << 4);
                const uint32_t swz1 = (uint32_t)((ph ^ (lc + 1)) << 4);
                #pragma unroll
                for (int nt = 0; nt < 8; ++nt) {
                    int c0 = nt * 8 + lc;
                    int4 b0 = *(const int4*)(sp + 8192 + c0 * 128 + swz0);
                    int4 b1 = *(const int4*)(sp + 8192 + (c0 + 1) * 128 + swz1);
                    #pragma unroll
                    for (int h = 0; h < 2; ++h) {
                        dp4x4(acc[nt][h * 2 + 0], av[h], b0);
                        dp4x4(acc[nt][h * 2 + 1], av[h], b1);
                    }
                }
            }
        }
    }

    const float wsd = g_wscale[2];
    const int r0 = lane >> 2, c0l = (lane & 3) * 2;
    #pragma unroll
    for (int half = 0; half < 2; ++half) {
        int row = mBase + warp * 16 + r0 + 8 * half;
        float f = wsd * g_hs[row];
        #pragma unroll
        for (int nt = 0; nt < 8; ++nt) {
            int col = nBase + nt * 8 + c0l;
            float2 ov;
            ov.x = (float)acc[nt][2 * half]     * f;
            ov.y = (float)acc[nt][2 * half + 1] * f;
            *(float2*)&out[(size_t)row * Hdim + col] = ov;
        }
    }
}

// ---------------- launch ----------------
extern "C" void kernel_launch(void* const* d_in, const int* in_sizes, int n_in,
                              void* d_out, int out_size) {
    const float* x  = (const float*)d_in[0];
    const float* wg = (const float*)d_in[1];
    const float* wu = (const float*)d_in[2];
    const float* wd = (const float*)d_in[3];
    float* out = (float*)d_out;
    (void)in_sizes; (void)n_in; (void)out_size;

    cudaFuncSetAttribute(gemm1_imma_kernel, cudaFuncAttributeMaxDynamicSharedMemorySize, 73728);
    cudaFuncSetAttribute(gemm2_imma_kernel, cudaFuncAttributeMaxDynamicSharedMemorySize, 49152);

    // launch #1: weight-scale partial sums
    abs_sum_partial_kernel<<<dim3(1024, 3), 256>>>((const float4*)wg, (const float4*)wu, (const float4*)wd);
    // launch #2: finalize scales
    finalize_scales_kernel<<<1, 256>>>();
    // launch #3: weight quant (y<3) + FWHT/quant of x (y==3)
    quant_fwht_kernel<<<dim3(4096, 4), 256>>>((const float4*)wg, (const float4*)wu, (const float4*)wd,
                                              (const float4*)x);
    // launch #4: hybrid gate/up GEMM + silu fuse  <-- ncu capture slot
    gemm1_imma_kernel<<<dim3(Idim / 32, Tdim / 128), 128, 73728>>>();
    // launch #5: FWHT + act quant of h
    fwht_quant_h_kernel<<<Tdim, 1024>>>();
    // launch #6: hybrid down projection
    gemm2_imma_kernel<<<dim3(Hdim / 64, Tdim / 64), 128, 49152>>>(out);
}

// round 16
// speedup vs baseline: 1.1135x; 1.1135x over previous
#include <cuda_runtime.h>
#include <cstdint>
#include <math.h>

#define EPSF 1e-5f

static constexpr int Hdim = 2048;   // hidden
static constexpr int Idim = 8192;   // intermediate
static constexpr int Tdim = 4096;   // B*S tokens
static constexpr int WELEMS = Hdim * Idim;

// ---------------- device scratch (no allocations allowed) ----------------
__device__ __align__(16) int8_t g_wq_gate[WELEMS];
__device__ __align__(16) int8_t g_wq_up[WELEMS];
__device__ __align__(16) int8_t g_wq_down[WELEMS];
__device__ __align__(16) int8_t g_xq[Tdim * Hdim];
__device__ float  g_xs[Tdim];
__device__ __align__(16) float  g_h[(size_t)Tdim * Idim];
__device__ __align__(16) int8_t g_hq[(size_t)Tdim * Idim];
__device__ float  g_hs[Tdim];
__device__ float  g_part[3 * 1024];
__device__ float  g_wscale[3];

// ---------------- small PTX helpers ----------------
__device__ __forceinline__ uint32_t smem_u32(const void* p) {
    return (uint32_t)__cvta_generic_to_shared(p);
}
__device__ __forceinline__ void cp_async16(uint32_t saddr, const void* gptr) {
    asm volatile("cp.async.cg.shared.global [%0], [%1], 16;\n" :: "r"(saddr), "l"(gptr));
}
__device__ __forceinline__ void cp_commit() {
    asm volatile("cp.async.commit_group;\n" ::: "memory");
}
template<int N>
__device__ __forceinline__ void cp_wait() {
    asm volatile("cp.async.wait_group %0;\n" :: "n"(N) : "memory");
}
__device__ __forceinline__ void ldsm_x4(uint32_t& r0, uint32_t& r1, uint32_t& r2, uint32_t& r3, uint32_t addr) {
    asm volatile("ldmatrix.sync.aligned.m8n8.x4.shared.b16 {%0,%1,%2,%3}, [%4];\n"
                 : "=r"(r0), "=r"(r1), "=r"(r2), "=r"(r3) : "r"(addr));
}
__device__ __forceinline__ void mma_s8(int* c, const uint32_t* a, const uint32_t* b) {
    asm volatile("mma.sync.aligned.m16n8k32.row.col.s32.s8.s8.s32 "
                 "{%0,%1,%2,%3}, {%4,%5,%6,%7}, {%8,%9}, {%0,%1,%2,%3};\n"
                 : "+r"(c[0]), "+r"(c[1]), "+r"(c[2]), "+r"(c[3])
                 : "r"(a[0]), "r"(a[1]), "r"(a[2]), "r"(a[3]), "r"(b[0]), "r"(b[1]));
}
__device__ __forceinline__ void dp4x4(int& acc, const int4& a, const int4& b) {
    acc = __dp4a(a.x, b.x, acc);
    acc = __dp4a(a.y, b.y, acc);
    acc = __dp4a(a.z, b.z, acc);
    acc = __dp4a(a.w, b.w, acc);
}

// ---------------- merged weight-scale partial sums (grid.y = widx) ----------------
__global__ void abs_sum_partial_kernel(const float4* __restrict__ w0,
                                       const float4* __restrict__ w1,
                                       const float4* __restrict__ w2) {
    __shared__ float sd[256];
    int widx = blockIdx.y;
    const float4* w4 = (widx == 0) ? w0 : (widx == 1) ? w1 : w2;
    int t = threadIdx.x;
    const float4* p = w4 + (size_t)blockIdx.x * 4096;
    float s = 0.f;
    #pragma unroll 4
    for (int i = t; i < 4096; i += 256) {
        float4 v = p[i];
        s += fabsf(v.x) + fabsf(v.y) + fabsf(v.z) + fabsf(v.w);
    }
    sd[t] = s;
    __syncthreads();
    for (int o = 128; o > 0; o >>= 1) {
        if (t < o) sd[t] += sd[t + o];
        __syncthreads();
    }
    if (t == 0) g_part[widx * 1024 + blockIdx.x] = sd[0];
}

__global__ void finalize_scales_kernel() {
    __shared__ float sd[256];
    int t = threadIdx.x;
    for (int w = 0; w < 3; ++w) {
        float s = g_part[w * 1024 + t] + g_part[w * 1024 + t + 256]
                + g_part[w * 1024 + t + 512] + g_part[w * 1024 + t + 768];
        sd[t] = s;
        __syncthreads();
        for (int o = 128; o > 0; o >>= 1) {
            if (t < o) sd[t] += sd[t + o];
            __syncthreads();
        }
        if (t == 0) {
            float mean = sd[0] / (float)WELEMS;
            g_wscale[w] = fmaxf(mean, EPSF);
        }
        __syncthreads();
    }
}

// ---------------- merged kernel: weight quant (y<3) + FWHT/quant of x (y==3) ----------------
__global__ __launch_bounds__(256)
void quant_fwht_kernel(const float4* __restrict__ w0,
                       const float4* __restrict__ w1,
                       const float4* __restrict__ w2,
                       const float4* __restrict__ x) {
    constexpr int N = 2048;
    constexpr int T = 256;
    constexpr int Q4 = N / 4;
    __shared__ float4 buf4[Q4];
    __shared__ float red[T / 32];

    const int t = threadIdx.x;

    if (blockIdx.y < 3) {
        if (blockIdx.x >= 2048) return;
        int widx = blockIdx.y;
        const float4* w4 = (widx == 0) ? w0 : (widx == 1) ? w1 : w2;
        char4* dst = (char4*)((widx == 0) ? g_wq_gate : (widx == 1) ? g_wq_up : g_wq_down);
        const float inv = 1.0f / g_wscale[widx];
        const int n4 = WELEMS / 4;
        const int stride = 2048 * 256;
        for (int i = blockIdx.x * 256 + t; i < n4; i += stride) {
            float4 v = w4[i];
            char4 o;
            o.x = (int8_t)fminf(fmaxf(rintf(v.x * inv), -1.f), 1.f);
            o.y = (int8_t)fminf(fmaxf(rintf(v.y * inv), -1.f), 1.f);
            o.z = (int8_t)fminf(fmaxf(rintf(v.z * inv), -1.f), 1.f);
            o.w = (int8_t)fminf(fmaxf(rintf(v.w * inv), -1.f), 1.f);
            dst[i] = o;
        }
        return;
    }

    const size_t row = blockIdx.x;
    const float4* xr = x + row * Q4;
    char4* q4 = (char4*)g_xq;

    float4 a = xr[2 * t], b = xr[2 * t + 1];
    float4 ta = make_float4(a.x + a.y, a.x - a.y, a.z + a.w, a.z - a.w);
    float4 tb = make_float4(b.x + b.y, b.x - b.y, b.z + b.w, b.z - b.w);
    a = make_float4(ta.x + ta.z, ta.y + ta.w, ta.x - ta.z, ta.y - ta.w);
    b = make_float4(tb.x + tb.z, tb.y + tb.w, tb.x - tb.z, tb.y - tb.w);
    buf4[2 * t] = a;
    buf4[2 * t + 1] = b;
    __syncthreads();

    #pragma unroll
    for (int hv = 1; hv <= N / 16; hv <<= 1) {
        int i4 = ((t & ~(hv - 1)) << 1) | (t & (hv - 1));
        float4 va = buf4[i4], vb = buf4[i4 + hv];
        buf4[i4]      = make_float4(va.x + vb.x, va.y + vb.y, va.z + vb.z, va.w + vb.w);
        buf4[i4 + hv] = make_float4(va.x - vb.x, va.y - vb.y, va.z - vb.z, va.w - vb.w);
        __syncthreads();
    }

    float4 va = buf4[t], vb = buf4[t + N / 8];
    const float c = (float)(1.0 / sqrt((double)N));
    float v0 = (va.x + vb.x) * c, v1 = (va.y + vb.y) * c;
    float v2 = (va.z + vb.z) * c, v3 = (va.w + vb.w) * c;
    float v4 = (va.x - vb.x) * c, v5 = (va.y - vb.y) * c;
    float v6 = (va.z - vb.z) * c, v7 = (va.w - vb.w) * c;

    float m = fmaxf(fmaxf(fmaxf(fabsf(v0), fabsf(v1)), fmaxf(fabsf(v2), fabsf(v3))),
                    fmaxf(fmaxf(fabsf(v4), fabsf(v5)), fmaxf(fabsf(v6), fabsf(v7))));
    #pragma unroll
    for (int o = 16; o; o >>= 1) m = fmaxf(m, __shfl_xor_sync(0xffffffffu, m, o));
    if ((t & 31) == 0) red[t >> 5] = m;
    __syncthreads();
    if (t < 32) {
        m = (t < T / 32) ? red[t] : 0.f;
        #pragma unroll
        for (int o = 16; o; o >>= 1) m = fmaxf(m, __shfl_xor_sync(0xffffffffu, m, o));
        if (t == 0) red[0] = fmaxf(m, EPSF);
    }
    __syncthreads();
    float absmax = red[0];
    float scale = 127.f / absmax;
    if (t == 0) g_xs[row] = absmax / 127.f;

    char4 o0, o1;
    o0.x = (int8_t)fminf(fmaxf(rintf(v0 * scale), -128.f), 127.f);
    o0.y = (int8_t)fminf(fmaxf(rintf(v1 * scale), -128.f), 127.f);
    o0.z = (int8_t)fminf(fmaxf(rintf(v2 * scale), -128.f), 127.f);
    o0.w = (int8_t)fminf(fmaxf(rintf(v3 * scale), -128.f), 127.f);
    o1.x = (int8_t)fminf(fmaxf(rintf(v4 * scale), -128.f), 127.f);
    o1.y = (int8_t)fminf(fmaxf(rintf(v5 * scale), -128.f), 127.f);
    o1.z = (int8_t)fminf(fmaxf(rintf(v6 * scale), -128.f), 127.f);
    o1.w = (int8_t)fminf(fmaxf(rintf(v7 * scale), -128.f), 127.f);
    q4[row * Q4 + t] = o0;
    q4[row * Q4 + t + N / 8] = o1;
}

// ---------------- FWHT(8192) + per-token int8 quant of h ----------------
__global__ __launch_bounds__(1024)
void fwht_quant_h_kernel() {
    constexpr int N = 8192;
    constexpr int T = N / 8;
    constexpr int Q4 = N / 4;
    __shared__ float4 buf4[Q4];
    __shared__ float red[T / 32];

    const float4* src4 = (const float4*)g_h;
    char4* q4 = (char4*)g_hq;

    const int t = threadIdx.x;
    const size_t row = blockIdx.x;
    const float4* x = src4 + row * Q4;

    float4 a = x[2 * t], b = x[2 * t + 1];
    float4 ta = make_float4(a.x + a.y, a.x - a.y, a.z + a.w, a.z - a.w);
    float4 tb = make_float4(b.x + b.y, b.x - b.y, b.z + b.w, b.z - b.w);
    a = make_float4(ta.x + ta.z, ta.y + ta.w, ta.x - ta.z, ta.y - ta.w);
    b = make_float4(tb.x + tb.z, tb.y + tb.w, tb.x - tb.z, tb.y - tb.w);
    buf4[2 * t] = a;
    buf4[2 * t + 1] = b;
    __syncthreads();

    #pragma unroll
    for (int hv = 1; hv <= N / 16; hv <<= 1) {
        int i4 = ((t & ~(hv - 1)) << 1) | (t & (hv - 1));
        float4 va = buf4[i4], vb = buf4[i4 + hv];
        buf4[i4]      = make_float4(va.x + vb.x, va.y + vb.y, va.z + vb.z, va.w + vb.w);
        buf4[i4 + hv] = make_float4(va.x - vb.x, va.y - vb.y, va.z - vb.z, va.w - vb.w);
        __syncthreads();
    }

    float4 va = buf4[t], vb = buf4[t + N / 8];
    const float c = (float)(1.0 / sqrt((double)N));
    float v0 = (va.x + vb.x) * c, v1 = (va.y + vb.y) * c;
    float v2 = (va.z + vb.z) * c, v3 = (va.w + vb.w) * c;
    float v4 = (va.x - vb.x) * c, v5 = (va.y - vb.y) * c;
    float v6 = (va.z - vb.z) * c, v7 = (va.w - vb.w) * c;

    float m = fmaxf(fmaxf(fmaxf(fabsf(v0), fabsf(v1)), fmaxf(fabsf(v2), fabsf(v3))),
                    fmaxf(fmaxf(fabsf(v4), fabsf(v5)), fmaxf(fabsf(v6), fabsf(v7))));
    #pragma unroll
    for (int o = 16; o; o >>= 1) m = fmaxf(m, __shfl_xor_sync(0xffffffffu, m, o));
    if ((t & 31) == 0) red[t >> 5] = m;
    __syncthreads();
    if (t < 32) {
        m = red[t];
        #pragma unroll
        for (int o = 16; o; o >>= 1) m = fmaxf(m, __shfl_xor_sync(0xffffffffu, m, o));
        if (t == 0) red[0] = fmaxf(m, EPSF);
    }
    __syncthreads();
    float absmax = red[0];
    float scale = 127.f / absmax;
    if (t == 0) g_hs[row] = absmax / 127.f;

    char4 o0, o1;
    o0.x = (int8_t)fminf(fmaxf(rintf(v0 * scale), -128.f), 127.f);
    o0.y = (int8_t)fminf(fmaxf(rintf(v1 * scale), -128.f), 127.f);
    o0.z = (int8_t)fminf(fmaxf(rintf(v2 * scale), -128.f), 127.f);
    o0.w = (int8_t)fminf(fmaxf(rintf(v3 * scale), -128.f), 127.f);
    o1.x = (int8_t)fminf(fmaxf(rintf(v4 * scale), -128.f), 127.f);
    o1.y = (int8_t)fminf(fmaxf(rintf(v5 * scale), -128.f), 127.f);
    o1.z = (int8_t)fminf(fmaxf(rintf(v6 * scale), -128.f), 127.f);
    o1.w = (int8_t)fminf(fmaxf(rintf(v7 * scale), -128.f), 127.f);
    q4[row * Q4 + t] = o0;
    q4[row * Q4 + t + N / 8] = o1;
}

// ================= K-ROTATION HYBRID GEMM 1 (8 warps, SMSP-paired phases) =================
// CTA 128M x 32 h-cols, 256 threads (8 warps, warp tile 16M x 32h dual gate/up).
// phase = (kt + warp + (warp>>2)) & 1: warps w and w+4 share SMSP (w&3) and always
// run OPPOSITE engines -> every SMSP feeds tensor and fma pipes simultaneously,
// independent of CTA placement. 6 warps/SMSP (3 CTAs) hide LDS latency.
__global__ __launch_bounds__(256, 3)
void gemm1_imma_kernel() {
    extern __shared__ int8_t smem[];
    // per stage: A 128x128B @0 (16KB), Bg 32x128B @16384, Bu 32x128B @20480; stride 24576
    const int K = Hdim;
    const int tid = threadIdx.x;
    const int warp = tid >> 5, lane = tid & 31;
    const int mBase = blockIdx.y << 7;
    const int nBase = blockIdx.x << 5;
    const uint32_t sbase = smem_u32(smem);

    int accg[4][4] = {}, accu[4][4] = {};   // nt x frag, dual

    // loader: 256 threads; A 4 chunks, Bg/Bu 1 chunk each
    const int8_t* gA[4]; uint32_t oA[4];
    #pragma unroll
    for (int j = 0; j < 4; ++j) {
        int i = tid + 256 * j;
        int row = i >> 3, ch = i & 7;
        gA[j] = g_xq + (size_t)(mBase + row) * K + ch * 16;
        oA[j] = row * 128 + ((ch ^ (row & 7)) << 4);
    }
    const int8_t* gG; const int8_t* gU; uint32_t oB;
    {
        int row = tid >> 3, ch = tid & 7;
        gG = g_wq_gate + (size_t)(nBase + row) * K + ch * 16;
        gU = g_wq_up   + (size_t)(nBase + row) * K + ch * 16;
        oB = row * 128 + ((ch ^ (row & 7)) << 4);
    }
    auto load_stage = [&](int stage, int kt) {
        uint32_t sst = sbase + stage * 24576;
        #pragma unroll
        for (int j = 0; j < 4; ++j) cp_async16(sst + oA[j], gA[j] + kt);
        cp_async16(sst + 16384 + oB, gG + kt);
        cp_async16(sst + 20480 + oB, gU + kt);
    };

    // mma addressing: warp tile rows [warp*16, +16)
    const int rA = warp * 16 + (lane & 15);
    const uint32_t rowOffA = rA * 128, rx7A = rA & 7;
    uint32_t rowOffB[2], rx7B[2];
    #pragma unroll
    for (int g = 0; g < 2; ++g) {
        int r = g * 16 + (lane & 15);
        rowOffB[g] = r * 128; rx7B[g] = r & 7;
    }
    const uint32_t laneHi = lane >> 4;
    // dp4a addressing (same fragment elements)
    const int lr = lane >> 2, lc = (lane & 3) * 2;

    const int iters = K / 128;  // 16
    load_stage(0, 0); cp_commit();
    load_stage(1, 128); cp_commit();

    for (int kt = 0; kt < iters; ++kt) {
        cp_wait<1>();
        __syncthreads();
        int nk = kt + 2;
        if (nk < iters) load_stage(nk % 3, nk * 128);
        cp_commit();

        if (((kt + warp + (warp >> 2)) & 1) == 0) {
            // ---------- tensor-pipe k-tile ----------
            uint32_t sst = sbase + (kt % 3) * 24576;
            #pragma unroll
            for (int s = 0; s < 4; ++s) {
                uint32_t ch = 2 * s + laneHi;
                uint32_t af[4];
                ldsm_x4(af[0], af[1], af[2], af[3], sst + rowOffA + ((ch ^ rx7A) << 4));
                uint32_t bg[4][2], bu[4][2];
                #pragma unroll
                for (int g = 0; g < 2; ++g) {
                    uint32_t r0, r1, r2, r3;
                    ldsm_x4(r0, r1, r2, r3, sst + 16384 + rowOffB[g] + ((ch ^ rx7B[g]) << 4));
                    bg[2 * g][0] = r0; bg[2 * g][1] = r2;
                    bg[2 * g + 1][0] = r1; bg[2 * g + 1][1] = r3;
                    ldsm_x4(r0, r1, r2, r3, sst + 20480 + rowOffB[g] + ((ch ^ rx7B[g]) << 4));
                    bu[2 * g][0] = r0; bu[2 * g][1] = r2;
                    bu[2 * g + 1][0] = r1; bu[2 * g + 1][1] = r3;
                }
                #pragma unroll
                for (int nt = 0; nt < 4; ++nt) {
                    mma_s8(accg[nt], af, bg[nt]);
                    mma_s8(accu[nt], af, bu[nt]);
                }
            }
        } else {
            // ---------- dp4a (fma-pipe) k-tile: same fragment elements ----------
            const int8_t* sp = smem + (kt % 3) * 24576;
            #pragma unroll 1
            for (int ph = 0; ph < 8; ++ph) {
                int4 av[2];
                #pragma unroll
                for (int h = 0; h < 2; ++h) {
                    int row = warp * 16 + lr + h * 8;
                    av[h] = *(const int4*)(sp + row * 128 + ((ph ^ (row & 7)) << 4));
                }
                const uint32_t swz0 = (uint32_t)((ph ^ lc) << 4);
                const uint32_t swz1 = (uint32_t)((ph ^ (lc + 1)) << 4);
                #pragma unroll
                for (int nt = 0; nt < 4; ++nt) {
                    int c0 = nt * 8 + lc;
                    int4 bg0 = *(const int4*)(sp + 16384 + c0 * 128 + swz0);
                    int4 bg1 = *(const int4*)(sp + 16384 + (c0 + 1) * 128 + swz1);
                    int4 bu0 = *(const int4*)(sp + 20480 + c0 * 128 + swz0);
                    int4 bu1 = *(const int4*)(sp + 20480 + (c0 + 1) * 128 + swz1);
                    #pragma unroll
                    for (int h = 0; h < 2; ++h) {
                        dp4x4(accg[nt][h * 2 + 0], av[h], bg0);
                        dp4x4(accg[nt][h * 2 + 1], av[h], bg1);
                        dp4x4(accu[nt][h * 2 + 0], av[h], bu0);
                        dp4x4(accu[nt][h * 2 + 1], av[h], bu1);
                    }
                }
            }
        }
    }

    // epilogue: silu(gate)*up -> g_h
    const float wsg = g_wscale[0], wsu = g_wscale[1];
    const int r0 = lane >> 2, c0l = (lane & 3) * 2;
    #pragma unroll
    for (int half = 0; half < 2; ++half) {
        int row = mBase + warp * 16 + r0 + 8 * half;
        float xs = g_xs[row];
        float fg = wsg * xs, fu = wsu * xs;
        #pragma unroll
        for (int nt = 0; nt < 4; ++nt) {
            int col = nBase + nt * 8 + c0l;
            float gv0 = (float)accg[nt][2 * half]     * fg;
            float gv1 = (float)accg[nt][2 * half + 1] * fg;
            float uv0 = (float)accu[nt][2 * half]     * fu;
            float uv1 = (float)accu[nt][2 * half + 1] * fu;
            float2 hv;
            hv.x = (gv0 / (1.f + expf(-gv0))) * uv0;
            hv.y = (gv1 / (1.f + expf(-gv1))) * uv1;
            *(float2*)&g_h[(size_t)row * Idim + col] = hv;
        }
    }
}

// ================= K-ROTATION HYBRID GEMM 2 (8 warps, SMSP-paired phases) =================
// CTA 128M x 64N, 256 threads (8 warps, warp tile 16M x 64N).
__global__ __launch_bounds__(256, 3)
void gemm2_imma_kernel(float* __restrict__ out) {
    extern __shared__ int8_t smem[];
    // per stage: A 128x128B @0 (16KB), B 64x128B @16384 (8KB); stride 24576
    const int K = Idim;
    const int tid = threadIdx.x;
    const int warp = tid >> 5, lane = tid & 31;
    const int mBase = blockIdx.y << 7;
    const int nBase = blockIdx.x << 6;
    const uint32_t sbase = smem_u32(smem);

    int acc[8][4] = {};

    const int8_t* gA[4]; uint32_t oA[4];
    #pragma unroll
    for (int j = 0; j < 4; ++j) {
        int i = tid + 256 * j;
        int row = i >> 3, ch = i & 7;              // rows 0..127
        gA[j] = g_hq + (size_t)(mBase + row) * K + ch * 16;
        oA[j] = row * 128 + ((ch ^ (row & 7)) << 4);
    }
    const int8_t* gB[2]; uint32_t oB[2];
    #pragma unroll
    for (int j = 0; j < 2; ++j) {
        int i = tid + 256 * j;
        int row = i >> 3, ch = i & 7;              // rows 0..63
        gB[j] = g_wq_down + (size_t)(nBase + row) * K + ch * 16;
        oB[j] = 16384 + row * 128 + ((ch ^ (row & 7)) << 4);
    }
    auto load_stage = [&](int stage, int kt) {
        uint32_t sst = sbase + stage * 24576;
        #pragma unroll
        for (int j = 0; j < 4; ++j) cp_async16(sst + oA[j], gA[j] + kt);
        #pragma unroll
        for (int j = 0; j < 2; ++j) cp_async16(sst + oB[j], gB[j] + kt);
    };

    // mma addressing
    const int rA = warp * 16 + (lane & 15);
    const uint32_t rowOffA = rA * 128, rx7A = rA & 7;
    uint32_t rowOffB[4], rx7B[4];
    #pragma unroll
    for (int g = 0; g < 4; ++g) {
        int r = g * 16 + (lane & 15);
        rowOffB[g] = 16384 + r * 128; rx7B[g] = r & 7;
    }
    const uint32_t laneHi = lane >> 4;
    const int lr = lane >> 2, lc = (lane & 3) * 2;

    const int iters = K / 128;  // 64
    load_stage(0, 0); cp_commit();
    load_stage(1, 128); cp_commit();

    for (int kt = 0; kt < iters; ++kt) {
        cp_wait<1>();
        __syncthreads();
        int nk = kt + 2;
        if (nk < iters) load_stage(nk % 3, nk * 128);
        cp_commit();

        if (((kt + warp + (warp >> 2)) & 1) == 0) {
            // ---------- tensor-pipe k-tile ----------
            uint32_t sst = sbase + (kt % 3) * 24576;
            #pragma unroll
            for (int s = 0; s < 4; ++s) {
                uint32_t ch = 2 * s + laneHi;
                uint32_t af[4];
                ldsm_x4(af[0], af[1], af[2], af[3], sst + rowOffA + ((ch ^ rx7A) << 4));
                uint32_t bf[8][2];
                #pragma unroll
                for (int g = 0; g < 4; ++g) {
                    uint32_t r0, r1, r2, r3;
                    ldsm_x4(r0, r1, r2, r3, sst + rowOffB[g] + ((ch ^ rx7B[g]) << 4));
                    bf[2 * g][0] = r0; bf[2 * g][1] = r2;
                    bf[2 * g + 1][0] = r1; bf[2 * g + 1][1] = r3;
                }
                #pragma unroll
                for (int nt = 0; nt < 8; ++nt)
                    mma_s8(acc[nt], af, bf[nt]);
            }
        } else {
            // ---------- dp4a k-tile ----------
            const int8_t* sp = smem + (kt % 3) * 24576;
            #pragma unroll 1
            for (int ph = 0; ph < 8; ++ph) {
                int4 av[2];
                #pragma unroll
                for (int h = 0; h < 2; ++h) {
                    int row = warp * 16 + lr + h * 8;
                    av[h] = *(const int4*)(sp + row * 128 + ((ph ^ (row & 7)) << 4));
                }
                const uint32_t swz0 = (uint32_t)((ph ^ lc) << 4);
                const uint32_t swz1 = (uint32_t)((ph ^ (lc + 1)) << 4);
                #pragma unroll
                for (int nt = 0; nt < 8; ++nt) {
                    int c0 = nt * 8 + lc;
                    int4 b0 = *(const int4*)(sp + 16384 + c0 * 128 + swz0);
                    int4 b1 = *(const int4*)(sp + 16384 + (c0 + 1) * 128 + swz1);
                    #pragma unroll
                    for (int h = 0; h < 2; ++h) {
                        dp4x4(acc[nt][h * 2 + 0], av[h], b0);
                        dp4x4(acc[nt][h * 2 + 1], av[h], b1);
                    }
                }
            }
        }
    }

    const float wsd = g_wscale[2];
    const int r0 = lane >> 2, c0l = (lane & 3) * 2;
    #pragma unroll
    for (int half = 0; half < 2; ++half) {
        int row = mBase + warp * 16 + r0 + 8 * half;
        float f = wsd * g_hs[row];
        #pragma unroll
        for (int nt = 0; nt < 8; ++nt) {
            int col = nBase + nt * 8 + c0l;
            float2 ov;
            ov.x = (float)acc[nt][2 * half]     * f;
            ov.y = (float)acc[nt][2 * half + 1] * f;
            *(float2*)&out[(size_t)row * Hdim + col] = ov;
        }
    }
}

// ---------------- launch ----------------
extern "C" void kernel_launch(void* const* d_in, const int* in_sizes, int n_in,
                              void* d_out, int out_size) {
    const float* x  = (const float*)d_in[0];
    const float* wg = (const float*)d_in[1];
    const float* wu = (const float*)d_in[2];
    const float* wd = (const float*)d_in[3];
    float* out = (float*)d_out;
    (void)in_sizes; (void)n_in; (void)out_size;

    cudaFuncSetAttribute(gemm1_imma_kernel, cudaFuncAttributeMaxDynamicSharedMemorySize, 73728);
    cudaFuncSetAttribute(gemm2_imma_kernel, cudaFuncAttributeMaxDynamicSharedMemorySize, 73728);

    // launch #1: weight-scale partial sums
    abs_sum_partial_kernel<<<dim3(1024, 3), 256>>>((const float4*)wg, (const float4*)wu, (const float4*)wd);
    // launch #2: finalize scales
    finalize_scales_kernel<<<1, 256>>>();
    // launch #3: weight quant (y<3) + FWHT/quant of x (y==3)
    quant_fwht_kernel<<<dim3(4096, 4), 256>>>((const float4*)wg, (const float4*)wu, (const float4*)wd,
                                              (const float4*)x);
    // launch #4: hybrid gate/up GEMM + silu fuse  <-- ncu capture slot
    gemm1_imma_kernel<<<dim3(Idim / 32, Tdim / 128), 256, 73728>>>();
    // launch #5: FWHT + act quant of h
    fwht_quant_h_kernel<<<Tdim, 1024>>>();
    // launch #6: hybrid down projection
    gemm2_imma_kernel<<<dim3(Hdim / 64, Tdim / 128), 256, 73728>>>(out);
}